// round 2
// baseline (speedup 1.0000x reference)
#include <cuda_runtime.h>

// Gini coefficient of an 8192-element fp32 vector.
// sum_{i,j}|x_i - x_j| is shift-invariant, so the min-shift only affects mu.
//
// K1: min + sum reduction
// K2: tiled O(n^2) pairwise abs-diff, per-block deterministic partials
// K3: deterministic tree reduce + finalize
//
// Scratch lives in __device__ globals (no allocation anywhere).

#define COL_CHUNK 1024      // columns per block tile (floats in smem)
#define ROWS_PER_BLK 512    // 256 threads x 2 rows each
#define MAX_BLK 1024        // generous upper bound on partial slots

__device__ float g_min_val;
__device__ float g_sum_val;
__device__ float g_part[MAX_BLK];

// ---------------- K1: min + sum ----------------
__global__ void k_min_sum(const float* __restrict__ x, int n) {
    __shared__ float smin[256];
    __shared__ float ssum[256];
    const int tid = threadIdx.x;
    float mn = 3.402823466e38f;
    float s  = 0.0f;
    for (int i = tid; i < n; i += 256) {
        float v = x[i];
        mn = fminf(mn, v);
        s += v;
    }
    smin[tid] = mn;
    ssum[tid] = s;
    __syncthreads();
    for (int off = 128; off > 0; off >>= 1) {
        if (tid < off) {
            smin[tid] = fminf(smin[tid], smin[tid + off]);
            ssum[tid] += ssum[tid + off];
        }
        __syncthreads();
    }
    if (tid == 0) {
        g_min_val = smin[0];
        g_sum_val = ssum[0];
    }
}

// ---------------- K2: pairwise |xi - xj| tile ----------------
// Grid: (n/ROWS_PER_BLK) * (n/COL_CHUNK) blocks, 256 threads.
// Block b: row chunk rc = b / ncc, col chunk cc = b % ncc.
// Each thread owns 2 rows (registers), iterates the col tile in smem via float4.
__global__ void k_pairwise(const float* __restrict__ x, int n) {
    __shared__ float4 sh[COL_CHUNK / 4];   // 4 KB col tile
    __shared__ float  red[256];

    const int tid = threadIdx.x;
    const int b   = blockIdx.x;
    const int ncc = n / COL_CHUNK;
    const int cc  = b % ncc;
    const int rc  = b / ncc;
    const int colBase = cc * COL_CHUNK;
    const int rowBase = rc * ROWS_PER_BLK;

    // cooperative float4 load of the column tile (coalesced)
    sh[tid] = reinterpret_cast<const float4*>(x + colBase)[tid];

    // two register-resident rows per thread (coalesced LDG)
    const float r0 = x[rowBase + tid];
    const float r1 = x[rowBase + 256 + tid];
    __syncthreads();

    float a0 = 0.0f, a1 = 0.0f;
#pragma unroll 8
    for (int j = 0; j < COL_CHUNK / 4; ++j) {
        const float4 v = sh[j];            // broadcast LDS.128
        a0 += fabsf(r0 - v.x);
        a1 += fabsf(r1 - v.x);
        a0 += fabsf(r0 - v.y);
        a1 += fabsf(r1 - v.y);
        a0 += fabsf(r0 - v.z);
        a1 += fabsf(r1 - v.z);
        a0 += fabsf(r0 - v.w);
        a1 += fabsf(r1 - v.w);
    }

    red[tid] = a0 + a1;
    __syncthreads();
    for (int off = 128; off > 0; off >>= 1) {
        if (tid < off) red[tid] += red[tid + off];
        __syncthreads();
    }
    if (tid == 0) g_part[b] = red[0];
}

// ---------------- K3: finalize ----------------
__global__ void k_finalize(float* __restrict__ out, int n, int nblk) {
    __shared__ float red[256];
    const int tid = threadIdx.x;
    float s = 0.0f;
    // deterministic fixed-order accumulation: tid-strided, then fixed tree
    for (int i = tid; i < nblk; i += 256) s += g_part[i];
    red[tid] = s;
    __syncthreads();
    for (int off = 128; off > 0; off >>= 1) {
        if (tid < off) red[tid] += red[tid + off];
        __syncthreads();
    }
    if (tid == 0) {
        const float nf = (float)n;
        float mean = g_sum_val / nf;
        if (g_min_val < 0.0f) mean -= g_min_val;   // mean(x - min) = mean(x) - min
        const float mu = mean + 1e-8f;
        out[0] = red[0] / (2.0f * nf * nf * mu);
    }
}

// ---------------- fallback for non-tileable n (defensive) ----------------
__global__ void k_pairwise_generic(const float* __restrict__ x, int n) {
    const int i = blockIdx.x * blockDim.x + threadIdx.x;
    float a = 0.0f;
    if (i < n) {
        const float xi = x[i];
        for (int j = 0; j < n; ++j) a += fabsf(xi - x[j]);
    }
    __shared__ float red[256];
    red[threadIdx.x] = a;
    __syncthreads();
    for (int off = 128; off > 0; off >>= 1) {
        if (threadIdx.x < off) red[threadIdx.x] += red[threadIdx.x + off];
        __syncthreads();
    }
    if (threadIdx.x == 0) g_part[blockIdx.x] = red[0];
}

extern "C" void kernel_launch(void* const* d_in, const int* in_sizes, int n_in,
                              void* d_out, int out_size) {
    const float* x = (const float*)d_in[0];
    float* out = (float*)d_out;
    const int n = in_sizes[0];

    k_min_sum<<<1, 256>>>(x, n);

    if (n % COL_CHUNK == 0 && n % ROWS_PER_BLK == 0 &&
        (n / ROWS_PER_BLK) * (n / COL_CHUNK) <= MAX_BLK) {
        const int nblk = (n / ROWS_PER_BLK) * (n / COL_CHUNK);  // 128 for n=8192
        k_pairwise<<<nblk, 256>>>(x, n);
        k_finalize<<<1, 256>>>(out, n, nblk);
    } else {
        const int nblk = (n + 255) / 256;
        k_pairwise_generic<<<nblk, 256>>>(x, n);
        k_finalize<<<1, 256>>>(out, n, nblk);
    }
}

// round 3
// speedup vs baseline: 1.5714x; 1.5714x over previous
#include <cuda_runtime.h>
#include <cstdint>

// Gini of n=8192 fp32 vector, single fused kernel.
//
// sum_{i,j}|xi-xj| is shift-invariant => the min-shift only affects mu.
// Tile the 8192x8192 pair matrix into 16x16 chunks of 512x512; by symmetry
// only the 136 upper-triangular tiles are computed (off-diag weighted 2x).
// 136 blocks ~= one block per SM (148 SMs), one wave.
//
// Math per 2 columns: packed add.rn.f32x2 with NEGATED column tile (diff),
// 64-bit AND for abs (alu pipe, parallel to fma pipe), packed accumulate.
//
// Last-block-done pattern fuses the partial reduce + min/sum + finalize.
// Counter resets itself => graph-replay safe. No allocations anywhere.

#define T_CHUNKS 16
#define NTILES   (T_CHUNKS * (T_CHUNKS + 1) / 2)   // 136
#define CHUNK    512
#define THREADS  256
#define GEN_MAX  4096

__device__ float        g_part[NTILES > GEN_MAX ? NTILES : GEN_MAX];
__device__ unsigned int g_count = 0;

__device__ __forceinline__ uint64_t pack2(float lo, float hi) {
    uint64_t r;
    asm("mov.b64 %0, {%1, %2};" : "=l"(r) : "f"(lo), "f"(hi));
    return r;
}
__device__ __forceinline__ uint64_t addf32x2(uint64_t a, uint64_t b) {
    uint64_t r;
    asm("add.rn.f32x2 %0, %1, %2;" : "=l"(r) : "l"(a), "l"(b));
    return r;
}
__device__ __forceinline__ float unpack_sum(uint64_t a) {
    float lo, hi;
    asm("mov.b64 {%0, %1}, %2;" : "=f"(lo), "=f"(hi) : "l"(a));
    return lo + hi;
}

__device__ __forceinline__ void finalize_last(const float* __restrict__ x, int n,
                                              float* __restrict__ out,
                                              int nblk, float* red, float* smin) {
    const int tid = threadIdx.x;
    // fixed-order reduce of partials
    float s = 0.0f;
    for (int i = tid; i < nblk; i += THREADS) s += g_part[i];
    red[tid] = s;
    __syncthreads();
    for (int off = THREADS / 2; off > 0; off >>= 1) {
        if (tid < off) red[tid] += red[tid + off];
        __syncthreads();
    }
    const float S = red[0];
    __syncthreads();
    // min + sum of x (fixed order, L2-resident by now)
    float mn = 3.402823466e38f, sm = 0.0f;
    for (int i = tid; i < n; i += THREADS) {
        float v = x[i];
        mn = fminf(mn, v);
        sm += v;
    }
    red[tid] = sm;
    smin[tid] = mn;
    __syncthreads();
    for (int off = THREADS / 2; off > 0; off >>= 1) {
        if (tid < off) {
            red[tid] += red[tid + off];
            smin[tid] = fminf(smin[tid], smin[tid + off]);
        }
        __syncthreads();
    }
    if (tid == 0) {
        const float nf = (float)n;
        float mean = red[0] / nf;
        if (smin[0] < 0.0f) mean -= smin[0];      // mean(x - min)
        out[0] = S / (2.0f * nf * nf * (mean + 1e-8f));
        g_count = 0;                               // reset for next replay
    }
}

// ---------------- fused pairwise kernel (n == 8192 path) ----------------
__global__ __launch_bounds__(THREADS, 1)
void k_gini(const float* __restrict__ x, float* __restrict__ out, int n) {
    __shared__ float2 sh[CHUNK / 2];     // negated column tile (2 KB)
    __shared__ float  red[THREADS];
    __shared__ float  smin[THREADS];
    __shared__ unsigned int isLast;

    const int tid = threadIdx.x;

    // triangular tile mapping: b -> (rc, cc), rc <= cc
    int rc = 0, rem = blockIdx.x;
    while (rem >= T_CHUNKS - rc) { rem -= (T_CHUNKS - rc); rc++; }
    const int cc = rc + rem;
    const int colBase = cc * CHUNK;
    const int rowBase = rc * CHUNK;

    // cooperative load of negated column tile (coalesced LDG.64)
    {
        float2 v = reinterpret_cast<const float2*>(x + colBase)[tid];
        sh[tid] = make_float2(-v.x, -v.y);
    }
    // two register rows per thread, packed (r, r)
    const float r0 = x[rowBase + tid];
    const float r1 = x[rowBase + THREADS + tid];
    const uint64_t rp0 = pack2(r0, r0);
    const uint64_t rp1 = pack2(r1, r1);
    __syncthreads();

    const uint64_t MASK = 0x7FFFFFFF7FFFFFFFULL;
    uint64_t a0x = 0, a0y = 0, a1x = 0, a1y = 0;   // split chains
    const ulonglong2* shq = reinterpret_cast<const ulonglong2*>(sh);

#pragma unroll 16
    for (int j = 0; j < CHUNK / 4; ++j) {
        const ulonglong2 c = shq[j];               // LDS.128 broadcast
        uint64_t d;
        d = addf32x2(rp0, c.x) & MASK;  a0x = addf32x2(a0x, d);
        d = addf32x2(rp0, c.y) & MASK;  a0y = addf32x2(a0y, d);
        d = addf32x2(rp1, c.x) & MASK;  a1x = addf32x2(a1x, d);
        d = addf32x2(rp1, c.y) & MASK;  a1y = addf32x2(a1y, d);
    }

    float mysum = unpack_sum(addf32x2(a0x, a0y)) + unpack_sum(addf32x2(a1x, a1y));

    red[tid] = mysum;
    __syncthreads();
    for (int off = THREADS / 2; off > 0; off >>= 1) {
        if (tid < off) red[tid] += red[tid + off];
        __syncthreads();
    }
    if (tid == 0) {
        float p = red[0];
        if (rc != cc) p *= 2.0f;                   // symmetry weight
        g_part[blockIdx.x] = p;
        __threadfence();
        unsigned int c = atomicAdd(&g_count, 1u);
        isLast = (c == gridDim.x - 1) ? 1u : 0u;
    }
    __syncthreads();

    if (isLast) {
        __threadfence();
        finalize_last(x, n, out, gridDim.x, red, smin);
    }
}

// ---------------- generic fallback (any n) ----------------
__global__ void k_gini_generic(const float* __restrict__ x, float* __restrict__ out, int n) {
    __shared__ float red[THREADS];
    __shared__ float smin[THREADS];
    __shared__ unsigned int isLast;
    const int tid = threadIdx.x;
    const int i = blockIdx.x * THREADS + tid;
    float a = 0.0f;
    if (i < n) {
        const float xi = x[i];
        for (int j = 0; j < n; ++j) a += fabsf(xi - x[j]);
    }
    red[tid] = a;
    __syncthreads();
    for (int off = THREADS / 2; off > 0; off >>= 1) {
        if (tid < off) red[tid] += red[tid + off];
        __syncthreads();
    }
    if (tid == 0) {
        g_part[blockIdx.x] = red[0];
        __threadfence();
        unsigned int c = atomicAdd(&g_count, 1u);
        isLast = (c == gridDim.x - 1) ? 1u : 0u;
    }
    __syncthreads();
    if (isLast) {
        __threadfence();
        finalize_last(x, n, out, gridDim.x, red, smin);
    }
}

extern "C" void kernel_launch(void* const* d_in, const int* in_sizes, int n_in,
                              void* d_out, int out_size) {
    const float* x = (const float*)d_in[0];
    float* out = (float*)d_out;
    const int n = in_sizes[0];

    if (n == T_CHUNKS * CHUNK) {
        k_gini<<<NTILES, THREADS>>>(x, out, n);
    } else {
        int nblk = (n + THREADS - 1) / THREADS;
        if (nblk > GEN_MAX) nblk = GEN_MAX;        // defensive cap (not hit for this problem)
        k_gini_generic<<<nblk, THREADS>>>(x, out, n);
    }
}